// round 6
// baseline (speedup 1.0000x reference)
#include <cuda_runtime.h>
#include <math.h>

// Problem constants
#define BB   16
#define CI   64
#define CO   64
#define SS   256
#define MM1  32
#define MM2  32
#define NR   63            // 2*m1-1 fx modes (fx = r-31)
#define NMODE (NR*MM2)     // 2016
#define NBI  (BB*CI)       // 1024
#define NBO  (BB*CO)       // 1024
#define KKC  64            // 2*MM2 interleaved re/im columns

typedef unsigned long long u64t;

// ---- packed f32x2 helpers (FFMA2 path, Blackwell-only via PTX) ----
__device__ __forceinline__ u64t pk(float lo, float hi) {
    u64t r;
    asm("mov.b64 %0, {%1, %2};" : "=l"(r)
        : "r"(__float_as_uint(lo)), "r"(__float_as_uint(hi)));
    return r;
}
__device__ __forceinline__ u64t pk2(float v) { return pk(v, v); }
__device__ __forceinline__ float2 upk(u64t v) {
    unsigned lo, hi;
    asm("mov.b64 {%0, %1}, %2;" : "=r"(lo), "=r"(hi) : "l"(v));
    return make_float2(__uint_as_float(lo), __uint_as_float(hi));
}
__device__ __forceinline__ void fma2(u64t& d, u64t a, u64t b) {
    asm("fma.rn.f32x2 %0, %1, %2, %3;" : "=l"(d) : "l"(a), "l"(b), "l"(d));
}

// -------- device scratch --------
__device__ __align__(16) float g_tab[512];                    // cos[0..255], sin[256..511]
__device__ __align__(16) u64t  g_cc[256];                     // {c,c}
__device__ __align__(16) u64t  g_ss[256];                     // {s,s}
__device__ __align__(16) u64t  g_nss[256];                    // {-s,-s}
__device__ __align__(16) u64t  g_nsps[256];                   // {-s,s}
__device__ __align__(16) float g_TP[(size_t)NBI * SS * KKC];  // stage1 out T, reused as stage4 out P
__device__ __align__(16) float g_G [(size_t)NBI * 16384];     // radix-16 intermediate (planes R then I)
__device__ __align__(16) float g_M1[(size_t)NBI * NMODE * 2]; // [bi][mode][2]
__device__ __align__(16) float g_W [(size_t)NMODE * CI * CO * 2]; // [mode][i*64+o][2] (scaled)
__device__ __align__(16) float g_M2[(size_t)NMODE * NBO * 2]; // [mode][b*64+o][2]

// ======================= K0: trig table =======================
__global__ void k_tab() {
    int n = threadIdx.x;
    double a = 2.0 * M_PI * (double)n / 256.0;
    float c = (float)cos(a), s = (float)sin(a);
    g_tab[n]       = c;
    g_tab[256 + n] = s;
    g_cc[n]   = pk2(c);
    g_ss[n]   = pk2(s);
    g_nss[n]  = pk2(-s);
    g_nsps[n] = pk(-s, s);
}

// ======================= K1: weight build + transpose =======================
__global__ void k_wbuild(const float* __restrict__ y0r, const float* __restrict__ y0i,
                         const float* __restrict__ ypr, const float* __restrict__ ypi,
                         const float* __restrict__ w00) {
    __shared__ float2 tile[32][33];
    int m0 = blockIdx.x * 32, io0 = blockIdx.y * 32;
    int tx = threadIdx.x, ty = threadIdx.y;   // 32 x 8
    #pragma unroll
    for (int q = 0; q < 4; q++) {
        int io = io0 + ty + 8 * q;
        int m  = m0 + tx;
        int r = m >> 5, k = m & 31;
        float wr, wi;
        if (k == 0) {
            if (r < 31)       { wr = y0r[io * 31 + r];        wi =  y0i[io * 31 + r]; }
            else if (r == 31) { wr = w00[io];                 wi =  0.f; }
            else              { wr = y0r[io * 31 + (62 - r)]; wi = -y0i[io * 31 + (62 - r)]; }
        } else {
            int idx = (io * 63 + r) * 31 + (k - 1);
            wr = ypr[idx]; wi = ypi[idx];
        }
        float sc = (k == 0 ? 1.0f : 2.0f) * (1.0f / 65536.0f);
        tile[ty + 8 * q][tx] = make_float2(wr * sc, wi * sc);
    }
    __syncthreads();
    #pragma unroll
    for (int q = 0; q < 4; q++) {
        int m  = m0 + ty + 8 * q;
        int io = io0 + tx;
        float2 w = tile[tx][ty + 8 * q];
        ((float2*)g_W)[(size_t)m * 4096 + io] = w;
    }
}

// ======================= K2: stage1 column DFT (GEMM 262144x64x256) =======================
__global__ void __launch_bounds__(256) k_s1(const float* __restrict__ x) {
    extern __shared__ float sm[];
    float* As = sm;                 // [32][257] transposed A tile
    float* Es = sm + 32 * 257;      // [256][64]
    for (int idx = threadIdx.x; idx < 256 * 64; idx += 256) {
        int v = idx >> 6, kk = idx & 63, ky = kk >> 1;
        int a = (ky * v) & 255;
        Es[idx] = (kk & 1) ? -g_tab[256 + a] : g_tab[a];
    }
    int row0 = blockIdx.x * 256;
    int i = threadIdx.x & 31, j = threadIdx.x >> 5;
    u64t acc2[8][4];
    #pragma unroll
    for (int t = 0; t < 8; t++)
        #pragma unroll
        for (int p = 0; p < 4; p++) acc2[t][p] = 0ULL;

    for (int k0 = 0; k0 < 256; k0 += 32) {
        __syncthreads();
        const float4* src = (const float4*)(x + (size_t)(row0 + threadIdx.x) * 256 + k0);
        #pragma unroll
        for (int q = 0; q < 8; q++) {
            float4 v4 = src[q];
            As[(q * 4 + 0) * 257 + threadIdx.x] = v4.x;
            As[(q * 4 + 1) * 257 + threadIdx.x] = v4.y;
            As[(q * 4 + 2) * 257 + threadIdx.x] = v4.z;
            As[(q * 4 + 3) * 257 + threadIdx.x] = v4.w;
        }
        __syncthreads();
        #pragma unroll 4
        for (int k = 0; k < 32; k++) {
            u64t a2[8], b2[4];
            #pragma unroll
            for (int t = 0; t < 8; t++) a2[t] = pk2(As[k * 257 + i + 32 * t]);
            #pragma unroll
            for (int p = 0; p < 4; p++)
                b2[p] = *(const u64t*)&Es[(k0 + k) * 64 + 2 * (j + 8 * p)];
            #pragma unroll
            for (int t = 0; t < 8; t++)
                #pragma unroll
                for (int p = 0; p < 4; p++) fma2(acc2[t][p], a2[t], b2[p]);
        }
    }
    __syncthreads();
    float* sC = sm;  // [256][65]
    #pragma unroll
    for (int t = 0; t < 8; t++)
        #pragma unroll
        for (int p = 0; p < 4; p++) {
            float2 up = upk(acc2[t][p]);
            int c = 2 * (j + 8 * p);
            sC[(i + 32 * t) * 65 + c]     = up.x;
            sC[(i + 32 * t) * 65 + c + 1] = up.y;
        }
    __syncthreads();
    for (int f = threadIdx.x; f < 256 * 16; f += 256) {
        int r = f >> 4, c4 = (f & 15) * 4;
        float4 v4 = make_float4(sC[r * 65 + c4], sC[r * 65 + c4 + 1],
                                sC[r * 65 + c4 + 2], sC[r * 65 + c4 + 3]);
        ((float4*)(g_TP + (size_t)(row0 + r) * 64))[f & 15] = v4;
    }
}

// ======================= K2a: stage2 radix pass A =======================
// G[km][u1][ky] = sum_{u0<16} T[u1+16*u0][ky] * e^{-2pi i km u0/16}
__global__ void __launch_bounds__(512) k_s2a() {
    extern __shared__ float sm[];
    float* Tr = sm;              // [256][34]
    float* Ti = sm + 256 * 34;   // [256][34]
    __shared__ u64t cc16[16], ss16[16], nss16[16];
    int bi = blockIdx.x;
    if (threadIdx.x < 16) {
        int j = threadIdx.x;
        float c = g_tab[(16 * j) & 255], s = g_tab[256 + 16 * j];
        cc16[j] = pk2(c); ss16[j] = pk2(s); nss16[j] = pk2(-s);
    }
    const float4* src = (const float4*)(g_TP + (size_t)bi * SS * KKC);
    for (int f = threadIdx.x; f < 256 * 16; f += 512) {
        float4 v = src[f];
        int u = f >> 4, k4 = f & 15;
        Tr[u * 34 + 2 * k4]     = v.x;  Ti[u * 34 + 2 * k4]     = v.y;
        Tr[u * 34 + 2 * k4 + 1] = v.z;  Ti[u * 34 + 2 * k4 + 1] = v.w;
    }
    __syncthreads();
    int kh = threadIdx.x & 1, u1 = (threadIdx.x >> 1) & 15, km = threadIdx.x >> 5;
    u64t aR[8], aI[8];
    #pragma unroll
    for (int p = 0; p < 8; p++) { aR[p] = 0ULL; aI[p] = 0ULL; }
    #pragma unroll
    for (int u0 = 0; u0 < 16; u0++) {
        int u = u1 + 16 * u0;
        int j = (km * u0) & 15;
        u64t c = cc16[j], s = ss16[j], ns = nss16[j];
        const float* trp = &Tr[u * 34 + kh * 16];
        const float* tip = &Ti[u * 34 + kh * 16];
        #pragma unroll
        for (int p = 0; p < 8; p++) {
            u64t tr = *(const u64t*)(trp + 2 * p);
            u64t ti = *(const u64t*)(tip + 2 * p);
            fma2(aR[p], tr, c); fma2(aR[p], ti, s);
            fma2(aI[p], ti, c); fma2(aI[p], tr, ns);
        }
    }
    float* gr = g_G + (size_t)bi * 16384 + km * 512 + u1 * 32 + kh * 16;
    float* gi = gr + 8192;
    #pragma unroll
    for (int p = 0; p < 8; p++) {
        *(u64t*)(gr + 2 * p) = aR[p];
        *(u64t*)(gi + 2 * p) = aI[p];
    }
}

// ======================= K2b: stage2 radix pass B =======================
// M1[r*32+ky] = sum_{u1<16} G[(r+1)&15][u1][ky] * e^{-2pi i (r-31) u1/256}
// NOTE: Gr/Gi row stride 516 floats = 2064 bytes (multiple of 16) so the
// float4 staging stores stay 16B-aligned for every km row.
#define GSTRIDE 516
__global__ void __launch_bounds__(256) k_s2b() {
    extern __shared__ float sm[];
    float* Gr = sm;                    // [16 km][GSTRIDE]
    float* Gi = sm + 16 * GSTRIDE;     // [16 km][GSTRIDE]
    __shared__ u64t ccS[256], ssS[256], nssS[256];
    int bi = blockIdx.x;
    for (int idx = threadIdx.x; idx < 256; idx += 256) {
        ccS[idx] = g_cc[idx]; ssS[idx] = g_ss[idx]; nssS[idx] = g_nss[idx];
    }
    {
        const float4* srcR = (const float4*)(g_G + (size_t)bi * 16384);
        const float4* srcI = srcR + 2048;
        for (int f4 = threadIdx.x; f4 < 2048; f4 += 256) {
            int km = f4 >> 7, off = (f4 & 127) * 4;
            *(float4*)&Gr[km * GSTRIDE + off] = srcR[f4];
            *(float4*)&Gi[km * GSTRIDE + off] = srcI[f4];
        }
    }
    __syncthreads();
    int r = threadIdx.x & 63, kq = threadIdx.x >> 6;  // kq<4, ky base kq*8
    int km = (r + 1) & 15;
    u64t aR[4], aI[4];
    #pragma unroll
    for (int p = 0; p < 4; p++) { aR[p] = 0ULL; aI[p] = 0ULL; }
    #pragma unroll
    for (int u1 = 0; u1 < 16; u1++) {
        int idx = ((r - 31) * u1) & 255;
        u64t c = ccS[idx], s = ssS[idx], ns = nssS[idx];
        const float* grp = &Gr[km * GSTRIDE + u1 * 32 + kq * 8];
        const float* gip = grp + 16 * GSTRIDE;
        #pragma unroll
        for (int p = 0; p < 4; p++) {
            u64t gr = *(const u64t*)(grp + 2 * p);
            u64t gi = *(const u64t*)(gip + 2 * p);
            fma2(aR[p], gr, c); fma2(aR[p], gi, s);
            fma2(aI[p], gi, c); fma2(aI[p], gr, ns);
        }
    }
    if (r < 63) {
        float2* out = (float2*)(g_M1 + ((size_t)bi * NMODE + r * 32 + kq * 8) * 2);
        #pragma unroll
        for (int p = 0; p < 4; p++) {
            float2 fR = upk(aR[p]), fI = upk(aI[p]);
            out[2 * p]     = make_float2(fR.x, fI.x);
            out[2 * p + 1] = make_float2(fR.y, fI.y);
        }
    }
}

// ======================= K4: stage3 channel mix per mode =======================
__global__ void __launch_bounds__(128) k_s3() {
    __shared__ float2 Ws[4096];
    __shared__ float2 Ms[1024];
    int m = blockIdx.x;
    {
        const float2* wsrc = (const float2*)g_W + (size_t)m * 4096;
        for (int idx = threadIdx.x; idx < 4096; idx += 128) Ws[idx] = wsrc[idx];
        const float2* msrc = (const float2*)g_M1;
        for (int idx = threadIdx.x; idx < 1024; idx += 128)
            Ms[idx] = msrc[(size_t)idx * NMODE + m];
    }
    __syncthreads();
    int o2 = threadIdx.x & 31, bg = threadIdx.x >> 5;
    u64t acc2[2][4];
    #pragma unroll
    for (int oo = 0; oo < 2; oo++)
        #pragma unroll
        for (int t = 0; t < 4; t++) acc2[oo][t] = 0ULL;
    for (int ii = 0; ii < 64; ii++) {
        float2 wa = Ws[ii * 64 + 2 * o2];
        float2 wb = Ws[ii * 64 + 2 * o2 + 1];
        u64t waP = pk(wa.x, wa.y), waN = pk(-wa.y, wa.x);
        u64t wbP = pk(wb.x, wb.y), wbN = pk(-wb.y, wb.x);
        #pragma unroll
        for (int t = 0; t < 4; t++) {
            float2 mm = Ms[(bg + 4 * t) * 64 + ii];
            u64t mdx = pk2(mm.x), mdy = pk2(mm.y);
            fma2(acc2[0][t], mdx, waP); fma2(acc2[0][t], mdy, waN);
            fma2(acc2[1][t], mdx, wbP); fma2(acc2[1][t], mdy, wbN);
        }
    }
    float2* out = (float2*)g_M2 + (size_t)m * 1024;
    #pragma unroll
    for (int t = 0; t < 4; t++)
        #pragma unroll
        for (int oo = 0; oo < 2; oo++) {
            float2 up = upk(acc2[oo][t]);
            out[(bg + 4 * t) * 64 + 2 * o2 + oo] = make_float2(up.x, up.y);
        }
}

// ======================= K5: stage4 radix-16 inverse (fused) =======================
// Pass A: C[km][s1][ky] = sum_{r: (r+1)&15==km} M2[r][ky] * e^{+2pi i (r-31) s1/256}
// Pass B: P[s1+16*s0][ky] = sum_{km<16} C[km][s1][ky] * e^{+2pi i km s0/16}
__global__ void __launch_bounds__(512) k_s4() {
    extern __shared__ float sm[];
    float* Mr = sm;                        // [63][34]
    float* Mi = sm + 63 * 34;              // [63][34]
    float* Cr = sm + 2 * 63 * 34;          // [16 km][544]
    float* Ci = Cr + 16 * 544;             // [16 km][544]
    __shared__ u64t ccS[256], ssS[256], nssS[256];
    __shared__ u64t cc16[16], ss16[16], nss16[16];
    int bo = blockIdx.x;
    if (threadIdx.x < 256) {
        int idx = threadIdx.x;
        ccS[idx] = g_cc[idx]; ssS[idx] = g_ss[idx]; nssS[idx] = g_nss[idx];
        if (idx < 16) {
            float c = g_tab[(16 * idx) & 255], s = g_tab[256 + 16 * idx];
            cc16[idx] = pk2(c); ss16[idx] = pk2(s); nss16[idx] = pk2(-s);
        }
    }
    {
        const float2* msrc = (const float2*)g_M2;
        for (int idx = threadIdx.x; idx < NMODE; idx += 512) {
            float2 v = msrc[(size_t)idx * 1024 + bo];
            int r = idx >> 5, ky = idx & 31;
            Mr[r * 34 + ky] = v.x;
            Mi[r * 34 + ky] = v.y;
        }
    }
    __syncthreads();
    // ---- pass A: thread = (km, s1, kh) ----
    {
        int kh = threadIdx.x & 1, s1 = (threadIdx.x >> 1) & 15, km = threadIdx.x >> 5;
        u64t aR[8], aI[8];
        #pragma unroll
        for (int p = 0; p < 8; p++) { aR[p] = 0ULL; aI[p] = 0ULL; }
        #pragma unroll
        for (int jj = 0; jj < 4; jj++) {
            int r = km - 1 + 16 * jj;
            if (r >= 0 && r < 63) {
                int idx = ((r - 31) * s1) & 255;
                u64t c = ccS[idx], s = ssS[idx], ns = nssS[idx];
                const float* mrp = &Mr[r * 34 + kh * 16];
                const float* mip = &Mi[r * 34 + kh * 16];
                #pragma unroll
                for (int p = 0; p < 8; p++) {
                    u64t mr = *(const u64t*)(mrp + 2 * p);
                    u64t mi = *(const u64t*)(mip + 2 * p);
                    fma2(aR[p], mr, c); fma2(aR[p], mi, ns);   // R += mr*c - mi*s
                    fma2(aI[p], mi, c); fma2(aI[p], mr, s);    // I += mi*c + mr*s
                }
            }
        }
        float* crp = &Cr[km * 544 + s1 * 34 + kh * 16];
        float* cip = &Ci[km * 544 + s1 * 34 + kh * 16];
        #pragma unroll
        for (int p = 0; p < 8; p++) {
            *(u64t*)(crp + 2 * p) = aR[p];
            *(u64t*)(cip + 2 * p) = aI[p];
        }
    }
    __syncthreads();
    // ---- pass B: thread = (s, kq) ----
    {
        int kq = threadIdx.x & 1, s = threadIdx.x >> 1;  // s<256
        int s1 = s & 15, s0 = s >> 4;
        u64t aR[8], aI[8];
        #pragma unroll
        for (int p = 0; p < 8; p++) { aR[p] = 0ULL; aI[p] = 0ULL; }
        #pragma unroll
        for (int km = 0; km < 16; km++) {
            int j = (km * s0) & 15;
            u64t c = cc16[j], ssv = ss16[j], ns = nss16[j];
            const float* crp = &Cr[km * 544 + s1 * 34 + kq * 16];
            const float* cip = &Ci[km * 544 + s1 * 34 + kq * 16];
            #pragma unroll
            for (int p = 0; p < 8; p++) {
                u64t cr = *(const u64t*)(crp + 2 * p);
                u64t ci = *(const u64t*)(cip + 2 * p);
                fma2(aR[p], cr, c); fma2(aR[p], ci, ns);   // R += cr*c - ci*s
                fma2(aI[p], ci, c); fma2(aI[p], cr, ssv);  // I += ci*c + cr*s
            }
        }
        float2* out = (float2*)(g_TP + (size_t)bo * SS * KKC) + s * 32 + kq * 16;
        #pragma unroll
        for (int p = 0; p < 8; p++) {
            float2 fR = upk(aR[p]), fI = upk(aI[p]);
            out[2 * p]     = make_float2(fR.x, fI.x);
            out[2 * p + 1] = make_float2(fR.y, fI.y);
        }
    }
}

// ======================= K6: stage5 inverse column (GEMM 262144x256x64) =======================
__global__ void __launch_bounds__(256) k_s5(float* __restrict__ y) {
    extern __shared__ float sm[];
    float* As = sm;                  // [64][65]
    float* Bs = sm + 64 * 65;        // [64][256]
    for (int idx = threadIdx.x; idx < 64 * 256; idx += 256) {
        int kk = idx >> 8, t = idx & 255, ky = kk >> 1;
        int a = (ky * t) & 255;
        Bs[idx] = (kk & 1) ? -g_tab[256 + a] : g_tab[a];
    }
    int row0 = blockIdx.x * 64;
    {
        const float4* src = (const float4*)(g_TP + (size_t)row0 * 64);
        for (int f = threadIdx.x; f < 1024; f += 256) {
            float4 v4 = src[f];
            int r = f >> 4, c4 = (f & 15) * 4;
            As[(c4 + 0) * 65 + r] = v4.x;
            As[(c4 + 1) * 65 + r] = v4.y;
            As[(c4 + 2) * 65 + r] = v4.z;
            As[(c4 + 3) * 65 + r] = v4.w;
        }
    }
    __syncthreads();
    int i = threadIdx.x & 15, j = threadIdx.x >> 4;
    u64t acc2[4][8];
    #pragma unroll
    for (int t = 0; t < 4; t++)
        #pragma unroll
        for (int p = 0; p < 8; p++) acc2[t][p] = 0ULL;
    #pragma unroll 2
    for (int k = 0; k < 64; k++) {
        u64t a2[4], b2[8];
        #pragma unroll
        for (int t = 0; t < 4; t++) a2[t] = pk2(As[k * 65 + i + 16 * t]);
        #pragma unroll
        for (int p = 0; p < 8; p++)
            b2[p] = *(const u64t*)&Bs[k * 256 + 2 * (j + 16 * p)];
        #pragma unroll
        for (int t = 0; t < 4; t++)
            #pragma unroll
            for (int p = 0; p < 8; p++) fma2(acc2[t][p], a2[t], b2[p]);
    }
    __syncthreads();
    float* sC = sm;  // [64][257]
    #pragma unroll
    for (int t = 0; t < 4; t++)
        #pragma unroll
        for (int p = 0; p < 8; p++) {
            float2 up = upk(acc2[t][p]);
            int c = 2 * (j + 16 * p);
            sC[(i + 16 * t) * 257 + c]     = up.x;
            sC[(i + 16 * t) * 257 + c + 1] = up.y;
        }
    __syncthreads();
    for (int f = threadIdx.x; f < 64 * 64; f += 256) {
        int r = f >> 6, c4 = (f & 63) * 4;
        float4 v4 = make_float4(sC[r * 257 + c4], sC[r * 257 + c4 + 1],
                                sC[r * 257 + c4 + 2], sC[r * 257 + c4 + 3]);
        ((float4*)(y + (size_t)(row0 + r) * 256))[f & 63] = v4;
    }
}

// ======================= launcher =======================
extern "C" void kernel_launch(void* const* d_in, const int* in_sizes, int n_in,
                              void* d_out, int out_size) {
    const float* x   = (const float*)d_in[0];
    const float* y0r = (const float*)d_in[1];
    const float* y0i = (const float*)d_in[2];
    const float* ypr = (const float*)d_in[3];
    const float* ypi = (const float*)d_in[4];
    const float* w00 = (const float*)d_in[5];
    float* y = (float*)d_out;

    const int smem_s1  = (32 * 257 + 256 * 64) * 4;
    const int smem_s2a = 2 * 256 * 34 * 4;
    const int smem_s2b = 2 * 16 * GSTRIDE * 4;
    const int smem_s4  = (2 * 63 * 34 + 2 * 16 * 544) * 4;
    const int smem_s5  = (64 * 65 + 64 * 256) * 4;

    cudaFuncSetAttribute(k_s1,  cudaFuncAttributeMaxDynamicSharedMemorySize, smem_s1);
    cudaFuncSetAttribute(k_s2a, cudaFuncAttributeMaxDynamicSharedMemorySize, smem_s2a);
    cudaFuncSetAttribute(k_s2b, cudaFuncAttributeMaxDynamicSharedMemorySize, smem_s2b);
    cudaFuncSetAttribute(k_s4,  cudaFuncAttributeMaxDynamicSharedMemorySize, smem_s4);
    cudaFuncSetAttribute(k_s5,  cudaFuncAttributeMaxDynamicSharedMemorySize, smem_s5);

    k_tab<<<1, 256>>>();
    k_wbuild<<<dim3(63, 128), dim3(32, 8)>>>(y0r, y0i, ypr, ypi, w00);
    k_s1<<<1024, 256, smem_s1>>>(x);
    k_s2a<<<1024, 512, smem_s2a>>>();
    k_s2b<<<1024, 256, smem_s2b>>>();
    k_s3<<<2016, 128>>>();
    k_s4<<<1024, 512, smem_s4>>>();
    k_s5<<<4096, 256, smem_s5>>>(y);
}

// round 8
// speedup vs baseline: 1.2975x; 1.2975x over previous
#include <cuda_runtime.h>
#include <math.h>

// Problem constants
#define BB   16
#define CI   64
#define CO   64
#define SS   256
#define MM1  32
#define MM2  32
#define NR   63            // 2*m1-1 fx modes (fx = r-31)
#define NMODE (NR*MM2)     // 2016
#define NBI  (BB*CI)       // 1024
#define NBO  (BB*CO)       // 1024
#define KKC  64            // 2*MM2 interleaved re/im columns

typedef unsigned long long u64t;

// ---- packed f32x2 helpers (FFMA2 path, Blackwell-only via PTX) ----
__device__ __forceinline__ u64t pk(float lo, float hi) {
    u64t r;
    asm("mov.b64 %0, {%1, %2};" : "=l"(r)
        : "r"(__float_as_uint(lo)), "r"(__float_as_uint(hi)));
    return r;
}
__device__ __forceinline__ u64t pk2(float v) { return pk(v, v); }
__device__ __forceinline__ float2 upk(u64t v) {
    unsigned lo, hi;
    asm("mov.b64 {%0, %1}, %2;" : "=r"(lo), "=r"(hi) : "l"(v));
    return make_float2(__uint_as_float(lo), __uint_as_float(hi));
}
__device__ __forceinline__ void fma2(u64t& d, u64t a, u64t b) {
    asm("fma.rn.f32x2 %0, %1, %2, %3;" : "=l"(d) : "l"(a), "l"(b), "l"(d));
}

// -------- device scratch --------
__device__ __align__(16) float g_tab[512];                    // cos[0..255], sin[256..511]
__device__ __align__(16) u64t  g_cc[256];                     // {c,c}
__device__ __align__(16) u64t  g_ss[256];                     // {s,s}
__device__ __align__(16) u64t  g_nsps[256];                   // {-s,s}
__device__ __align__(16) float g_TP[(size_t)NBI * SS * KKC];  // stage1 out T, reused as stage4 out P
__device__ __align__(16) float g_M1[(size_t)NBI * NMODE * 2]; // [bi][mode][2]
__device__ __align__(16) float g_W [(size_t)NMODE * CI * CO * 2]; // [mode][i*64+o][2] (scaled)
__device__ __align__(16) float g_M2[(size_t)NMODE * NBO * 2]; // [mode][b*64+o][2]

// ======================= K0: trig table =======================
__global__ void k_tab() {
    int n = threadIdx.x;
    double a = 2.0 * M_PI * (double)n / 256.0;
    float c = (float)cos(a), s = (float)sin(a);
    g_tab[n]       = c;
    g_tab[256 + n] = s;
    g_cc[n]   = pk2(c);
    g_ss[n]   = pk2(s);
    g_nsps[n] = pk(-s, s);
}

// ======================= K1: weight build + transpose =======================
__global__ void k_wbuild(const float* __restrict__ y0r, const float* __restrict__ y0i,
                         const float* __restrict__ ypr, const float* __restrict__ ypi,
                         const float* __restrict__ w00) {
    __shared__ float2 tile[32][33];
    int m0 = blockIdx.x * 32, io0 = blockIdx.y * 32;
    int tx = threadIdx.x, ty = threadIdx.y;   // 32 x 8
    #pragma unroll
    for (int q = 0; q < 4; q++) {
        int io = io0 + ty + 8 * q;
        int m  = m0 + tx;
        int r = m >> 5, k = m & 31;
        float wr, wi;
        if (k == 0) {
            if (r < 31)       { wr = y0r[io * 31 + r];        wi =  y0i[io * 31 + r]; }
            else if (r == 31) { wr = w00[io];                 wi =  0.f; }
            else              { wr = y0r[io * 31 + (62 - r)]; wi = -y0i[io * 31 + (62 - r)]; }
        } else {
            int idx = (io * 63 + r) * 31 + (k - 1);
            wr = ypr[idx]; wi = ypi[idx];
        }
        float sc = (k == 0 ? 1.0f : 2.0f) * (1.0f / 65536.0f);
        tile[ty + 8 * q][tx] = make_float2(wr * sc, wi * sc);
    }
    __syncthreads();
    #pragma unroll
    for (int q = 0; q < 4; q++) {
        int m  = m0 + ty + 8 * q;
        int io = io0 + tx;
        float2 w = tile[tx][ty + 8 * q];
        ((float2*)g_W)[(size_t)m * 4096 + io] = w;
    }
}

// ======================= K2: stage1 column DFT, k-pair packed =======================
// T[row][col] = sum_k x[row][k] * E[col][k], row=bi*256+u, col=2ky|2ky+1
// acc lanes hold {sum over even k, sum over odd k}; final = .x + .y
__global__ void __launch_bounds__(256, 2) k_s1(const float* __restrict__ x) {
    extern __shared__ float sm[];
    float* Es = sm;                 // [64][258]  (col-major in k, even stride)
    float* As = sm + 64 * 258;      // [128][34]
    for (int idx = threadIdx.x; idx < 64 * 256; idx += 256) {
        int col = idx >> 8, k = idx & 255;
        int ky = col >> 1;
        int a = (ky * k) & 255;
        Es[col * 258 + k] = (col & 1) ? -g_tab[256 + a] : g_tab[a];
    }
    int row0 = blockIdx.x * 128;
    int i = threadIdx.x & 31, j = threadIdx.x >> 5;   // i: row lane, j: col group (8 cols)
    u64t acc[4][8];
    #pragma unroll
    for (int t = 0; t < 4; t++)
        #pragma unroll
        for (int c = 0; c < 8; c++) acc[t][c] = 0ULL;

    for (int kb = 0; kb < 8; kb++) {
        int k0 = kb * 32;
        __syncthreads();
        #pragma unroll
        for (int q = 0; q < 4; q++) {
            int f = threadIdx.x + 256 * q;       // < 1024
            int r = f >> 3, kc = (f & 7) * 4;
            float4 v = *(const float4*)(x + (size_t)(row0 + r) * 256 + k0 + kc);
            *(u64t*)&As[r * 34 + kc]     = pk(v.x, v.y);
            *(u64t*)&As[r * 34 + kc + 2] = pk(v.z, v.w);
        }
        __syncthreads();
        #pragma unroll 4
        for (int kp = 0; kp < 16; kp++) {
            u64t a2[4], b2[8];
            #pragma unroll
            for (int t = 0; t < 4; t++)
                a2[t] = *(const u64t*)&As[(i + 32 * t) * 34 + 2 * kp];
            #pragma unroll
            for (int c = 0; c < 8; c++)
                b2[c] = *(const u64t*)&Es[(8 * j + c) * 258 + k0 + 2 * kp];
            #pragma unroll
            for (int t = 0; t < 4; t++)
                #pragma unroll
                for (int c = 0; c < 8; c++) fma2(acc[t][c], a2[t], b2[c]);
        }
    }
    #pragma unroll
    for (int t = 0; t < 4; t++) {
        int row = row0 + i + 32 * t;
        float v[8];
        #pragma unroll
        for (int c = 0; c < 8; c++) {
            float2 f2 = upk(acc[t][c]);
            v[c] = f2.x + f2.y;
        }
        float* dst = g_TP + (size_t)row * 64 + 8 * j;
        *(float4*)dst       = make_float4(v[0], v[1], v[2], v[3]);
        *(float4*)(dst + 4) = make_float4(v[4], v[5], v[6], v[7]);
    }
}

// ======================= K3: stage2 row DFT per image (deferred swizzle) =======================
// M1[bi][r*32+ky] = sum_u e^{-2pi i (r-31) u /256} * T[bi][u][ky]
// accA = sum {tr,ti}*c ; accB = sum {tr,ti}*s ; aR=A.x+B.y, aI=A.y-B.x
__global__ void __launch_bounds__(128, 3) k_s2() {
    extern __shared__ char smraw[];
    u64t* ccS = (u64t*)smraw;           // 256
    u64t* ssS = ccS + 256;              // 256
    float* Ts = (float*)(ssS + 256);    // [256][64] interleaved re/im
    int bi = blockIdx.x;
    for (int idx = threadIdx.x; idx < 256; idx += 128) {
        ccS[idx] = g_cc[idx];
        ssS[idx] = g_ss[idx];
    }
    {
        const float4* src = (const float4*)(g_TP + (size_t)bi * SS * KKC);
        for (int idx = threadIdx.x; idx < 256 * 16; idx += 128)
            ((float4*)Ts)[idx] = src[idx];
    }
    __syncthreads();
    int fxg = threadIdx.x & 15, kyg = threadIdx.x >> 4;  // 16 x 8
    u64t accA[4][4], accB[4][4];
    #pragma unroll
    for (int t = 0; t < 4; t++)
        #pragma unroll
        for (int s2 = 0; s2 < 4; s2++) { accA[t][s2] = 0ULL; accB[t][s2] = 0ULL; }

    #pragma unroll 2
    for (int u = 0; u < 256; u++) {
        u64t tv[4], cc[4], ss[4];
        #pragma unroll
        for (int s2 = 0; s2 < 4; s2++)
            tv[s2] = *(const u64t*)&Ts[(u * 32 + kyg + 8 * s2) * 2];
        #pragma unroll
        for (int t = 0; t < 4; t++) {
            int r = fxg + 16 * t;
            int idx = ((r - 31) * u) & 255;
            cc[t] = ccS[idx];
            ss[t] = ssS[idx];
        }
        #pragma unroll
        for (int t = 0; t < 4; t++)
            #pragma unroll
            for (int s2 = 0; s2 < 4; s2++) {
                fma2(accA[t][s2], tv[s2], cc[t]);
                fma2(accB[t][s2], tv[s2], ss[t]);
            }
    }
    float2* out = (float2*)(g_M1 + (size_t)bi * NMODE * 2);
    #pragma unroll
    for (int t = 0; t < 4; t++) {
        int r = fxg + 16 * t;
        if (r < 63) {
            #pragma unroll
            for (int s2 = 0; s2 < 4; s2++) {
                int ky = kyg + 8 * s2;
                float2 fa = upk(accA[t][s2]), fb = upk(accB[t][s2]);
                out[r * 32 + ky] = make_float2(fa.x + fb.y, fa.y - fb.x);
            }
        }
    }
}

// ======================= K4: stage3 channel mix per mode (role-swap) =======================
// M2[m][b][o] = sum_i M1[b][i][m] * W[m][i][o]   (complex)
// accA = sum {mx,my}*wx ; accB = sum {mx,my}*wy ; oR=A.x-B.y, oI=B.x+A.y
__global__ void __launch_bounds__(128) k_s3() {
    __shared__ float2 Ws[4096];
    __shared__ float2 Ms[1024];
    int m = blockIdx.x;
    {
        const float2* wsrc = (const float2*)g_W + (size_t)m * 4096;
        for (int idx = threadIdx.x; idx < 4096; idx += 128) Ws[idx] = wsrc[idx];
        const float2* msrc = (const float2*)g_M1;
        for (int idx = threadIdx.x; idx < 1024; idx += 128)
            Ms[idx] = msrc[(size_t)idx * NMODE + m];
    }
    __syncthreads();
    int o2 = threadIdx.x & 31, bg = threadIdx.x >> 5;  // o pair lane(32) x bg(4)
    u64t accA[2][4], accB[2][4];
    #pragma unroll
    for (int oo = 0; oo < 2; oo++)
        #pragma unroll
        for (int t = 0; t < 4; t++) { accA[oo][t] = 0ULL; accB[oo][t] = 0ULL; }
    for (int ii = 0; ii < 64; ii++) {
        float2 wa = Ws[ii * 64 + 2 * o2];
        float2 wb = Ws[ii * 64 + 2 * o2 + 1];
        u64t waxx = pk2(wa.x), wayy = pk2(wa.y);
        u64t wbxx = pk2(wb.x), wbyy = pk2(wb.y);
        #pragma unroll
        for (int t = 0; t < 4; t++) {
            u64t mm = *(const u64t*)&Ms[(bg + 4 * t) * 64 + ii];
            fma2(accA[0][t], mm, waxx); fma2(accB[0][t], mm, wayy);
            fma2(accA[1][t], mm, wbxx); fma2(accB[1][t], mm, wbyy);
        }
    }
    float2* out = (float2*)g_M2 + (size_t)m * 1024;
    #pragma unroll
    for (int t = 0; t < 4; t++)
        #pragma unroll
        for (int oo = 0; oo < 2; oo++) {
            float2 fa = upk(accA[oo][t]), fb = upk(accB[oo][t]);
            out[(bg + 4 * t) * 64 + 2 * o2 + oo] = make_float2(fa.x - fb.y, fb.x + fa.y);
        }
}

// ======================= K5: stage4 inverse row DFT per (b,o) =======================
// P[bo][s][ky] = sum_r M2[r*32+ky][bo] * e^{+2pi i (r-31) s/256}
__global__ void __launch_bounds__(512) k_s4() {
    __shared__ float2 Ms[NMODE];
    __shared__ u64t ccT[256], nspsT[256];
    int bo = blockIdx.x;
    for (int idx = threadIdx.x; idx < 256; idx += 512) {
        ccT[idx] = g_cc[idx];
        nspsT[idx] = g_nsps[idx];
    }
    {
        const float2* msrc = (const float2*)g_M2;
        for (int idx = threadIdx.x; idx < NMODE; idx += 512)
            Ms[idx] = msrc[(size_t)idx * 1024 + bo];
    }
    __syncthreads();
    int kyg = threadIdx.x & 7, sg = threadIdx.x >> 3;  // 8 x 64
    u64t acc2[4][4];   // {pR, pI}
    #pragma unroll
    for (int t = 0; t < 4; t++)
        #pragma unroll
        for (int u = 0; u < 4; u++) acc2[t][u] = 0ULL;

    for (int r = 0; r < 63; r++) {
        int fx = r - 31;
        u64t m2[4], msw[4], c2[4], sp[4];
        #pragma unroll
        for (int u = 0; u < 4; u++) {
            m2[u] = *(const u64t*)&Ms[r * 32 + kyg + 8 * u];
            float2 f = upk(m2[u]);
            msw[u] = pk(f.y, f.x);         // {mi, mr}
        }
        #pragma unroll
        for (int t = 0; t < 4; t++) {
            int s2 = sg + 64 * t;
            int idx = (fx * s2) & 255;
            c2[t] = ccT[idx];
            sp[t] = nspsT[idx];            // {-sn, sn}
        }
        #pragma unroll
        for (int t = 0; t < 4; t++)
            #pragma unroll
            for (int u = 0; u < 4; u++) {
                fma2(acc2[t][u], c2[t], m2[u]);   // pR+=c*mr,  pI+=c*mi
                fma2(acc2[t][u], sp[t], msw[u]);  // pR-=sn*mi, pI+=sn*mr
            }
    }
    float2* out = (float2*)(g_TP + (size_t)bo * SS * KKC);  // reuse T buffer as P
    #pragma unroll
    for (int t = 0; t < 4; t++)
        #pragma unroll
        for (int u = 0; u < 4; u++) {
            float2 up = upk(acc2[t][u]);
            out[(sg + 64 * t) * 32 + kyg + 8 * u] = make_float2(up.x, up.y);
        }
}

// ======================= K6: stage5 inverse column, k-pair packed =======================
// y[row][t] = sum_kk P[row][kk] * B[t][kk], kk = 64 interleaved re/im
__global__ void __launch_bounds__(256, 2) k_s5(float* __restrict__ y) {
    extern __shared__ float sm[];
    float* Bs = sm;                  // [64 local cols][66]
    float* As = sm + 64 * 66;        // [128 rows][66]
    int col0 = blockIdx.y * 64;
    for (int idx = threadIdx.x; idx < 64 * 64; idx += 256) {
        int cl = idx >> 6, kk = idx & 63;
        int t = col0 + cl;
        int ky = kk >> 1;
        int a = (ky * t) & 255;
        Bs[cl * 66 + kk] = (kk & 1) ? -g_tab[256 + a] : g_tab[a];
    }
    int row0 = blockIdx.x * 128;
    {
        #pragma unroll
        for (int q = 0; q < 8; q++) {
            int f = threadIdx.x + 256 * q;        // < 2048
            int r = f >> 4, kc = (f & 15) * 4;
            float4 v = *(const float4*)(g_TP + (size_t)(row0 + r) * 64 + kc);
            *(u64t*)&As[r * 66 + kc]     = pk(v.x, v.y);
            *(u64t*)&As[r * 66 + kc + 2] = pk(v.z, v.w);
        }
    }
    __syncthreads();
    int i = threadIdx.x & 31, j = threadIdx.x >> 5;   // i: row lane, j: col group (8)
    u64t acc[4][8];
    #pragma unroll
    for (int t = 0; t < 4; t++)
        #pragma unroll
        for (int c = 0; c < 8; c++) acc[t][c] = 0ULL;
    #pragma unroll 4
    for (int kp = 0; kp < 32; kp++) {
        u64t a2[4], b2[8];
        #pragma unroll
        for (int t = 0; t < 4; t++)
            a2[t] = *(const u64t*)&As[(i + 32 * t) * 66 + 2 * kp];
        #pragma unroll
        for (int c = 0; c < 8; c++)
            b2[c] = *(const u64t*)&Bs[(8 * j + c) * 66 + 2 * kp];
        #pragma unroll
        for (int t = 0; t < 4; t++)
            #pragma unroll
            for (int c = 0; c < 8; c++) fma2(acc[t][c], a2[t], b2[c]);
    }
    #pragma unroll
    for (int t = 0; t < 4; t++) {
        int row = row0 + i + 32 * t;
        float v[8];
        #pragma unroll
        for (int c = 0; c < 8; c++) {
            float2 f2 = upk(acc[t][c]);
            v[c] = f2.x + f2.y;
        }
        float* dst = y + (size_t)row * 256 + col0 + 8 * j;
        *(float4*)dst       = make_float4(v[0], v[1], v[2], v[3]);
        *(float4*)(dst + 4) = make_float4(v[4], v[5], v[6], v[7]);
    }
}

// ======================= launcher =======================
extern "C" void kernel_launch(void* const* d_in, const int* in_sizes, int n_in,
                              void* d_out, int out_size) {
    const float* x   = (const float*)d_in[0];
    const float* y0r = (const float*)d_in[1];
    const float* y0i = (const float*)d_in[2];
    const float* ypr = (const float*)d_in[3];
    const float* ypi = (const float*)d_in[4];
    const float* w00 = (const float*)d_in[5];
    float* y = (float*)d_out;

    const int smem_s1 = (64 * 258 + 128 * 34) * 4;            // 83456
    const int smem_s2 = 256 * 8 * 2 + 256 * 64 * 4;           // 69632
    const int smem_s5 = (64 * 66 + 128 * 66) * 4;             // 50688

    cudaFuncSetAttribute(k_s1, cudaFuncAttributeMaxDynamicSharedMemorySize, smem_s1);
    cudaFuncSetAttribute(k_s2, cudaFuncAttributeMaxDynamicSharedMemorySize, smem_s2);
    cudaFuncSetAttribute(k_s5, cudaFuncAttributeMaxDynamicSharedMemorySize, smem_s5);

    k_tab<<<1, 256>>>();
    k_wbuild<<<dim3(63, 128), dim3(32, 8)>>>(y0r, y0i, ypr, ypi, w00);
    k_s1<<<2048, 256, smem_s1>>>(x);
    k_s2<<<1024, 128, smem_s2>>>();
    k_s3<<<2016, 128>>>();
    k_s4<<<1024, 512>>>();
    k_s5<<<dim3(2048, 4), 256, smem_s5>>>(y);
}